// round 15
// baseline (speedup 1.0000x reference)
#include <cuda_runtime.h>
#include <cuda_fp16.h>
#include <math.h>
#include <stdint.h>

// ---------------------------------------------------------------------------
// Problem constants
// ---------------------------------------------------------------------------
#define HW     4096          // 64*64
#define NB     8
#define OUT_A_ELEMS (8 * 256 * 4096)   // "a" output
// output layout: a [8,256,64,64] followed by w [8,256]

// ---------------------------------------------------------------------------
// Scratch (static device globals -- no allocation allowed)
// ---------------------------------------------------------------------------
__device__ float g_sum [8 * 256];          // stage-A GAP accumulator
__device__ float g_w   [8 * 256];          // normalized channel weights

// fp16 channel-last activation planes [n*4096][C]
__device__ __align__(16) __half g_x1f [8ULL * 4096 * 256];
__device__ __align__(16) __half g_thxf[8ULL * 4096 * 256];
__device__ __align__(16) __half g_txuf[8ULL * 4096 * 256];
__device__ __align__(16) __half g_x2f [8ULL * 4096 * 256];
__device__ __align__(16) __half g_b1f [8ULL * 4096 * 256];
__device__ __align__(16) __half g_b2f [8ULL * 4096 * 128];
__device__ __align__(16) __half g_a1f [8ULL * 4096 * 128];
__device__ __align__(16) __half g_aT_f[8ULL * 4096 * 640];

// fp16 weights (row-major [O][K])
__device__ __align__(16) __half g_wt1[256 * 768];
__device__ __align__(16) __half g_wU [256 * 256];
__device__ __align__(16) __half g_wV [128 * 256];
__device__ __align__(16) __half g_wa1[128 * 640];
__device__ __align__(16) __half g_wa2[640 * 128];
// conv3x3 weights, tap-major [oc][tap*640+c]
__device__ __align__(16) __half g_wf[256 * 5760];

// ---------------------------------------------------------------------------
// helpers
// ---------------------------------------------------------------------------
__device__ __forceinline__ uint32_t smem_to_u32(const void* p) {
    uint32_t a;
    asm("{ .reg .u64 t; cvta.to.shared.u64 t, %1; cvt.u32.u64 %0, t; }"
        : "=r"(a) : "l"(p));
    return a;
}

__device__ __forceinline__ void cp16(uint32_t dst, const void* src, uint32_t bytes) {
    asm volatile("cp.async.cg.shared.global [%0], [%1], 16, %2;"
                 :: "r"(dst), "l"(src), "r"(bytes) : "memory");
}
__device__ __forceinline__ void cp_commit() {
    asm volatile("cp.async.commit_group;" ::: "memory");
}
template<int N>
__device__ __forceinline__ void cp_wait() {
    asm volatile("cp.async.wait_group %0;" :: "n"(N) : "memory");
}

__device__ __forceinline__ void ldm_x4(uint32_t (&r)[4], uint32_t addr) {
    asm volatile("ldmatrix.sync.aligned.m8n8.x4.shared.b16 {%0,%1,%2,%3}, [%4];"
                 : "=r"(r[0]), "=r"(r[1]), "=r"(r[2]), "=r"(r[3]) : "r"(addr));
}

__device__ __forceinline__ void mma_f16(float (&c)[4], const uint32_t (&a)[4],
                                        uint32_t b0, uint32_t b1) {
    asm volatile(
        "mma.sync.aligned.m16n8k16.row.col.f32.f16.f16.f32 "
        "{%0,%1,%2,%3}, {%4,%5,%6,%7}, {%8,%9}, {%0,%1,%2,%3};"
        : "+f"(c[0]), "+f"(c[1]), "+f"(c[2]), "+f"(c[3])
        : "r"(a[0]), "r"(a[1]), "r"(a[2]), "r"(a[3]), "r"(b0), "r"(b1));
}

// ---------------------------------------------------------------------------
// fused upsample x2 (align_corners) + transpose + fp16: tx -> g_txuf
// ---------------------------------------------------------------------------
__global__ __launch_bounds__(256) void ups_cvt_k(const float* __restrict__ tx)
{
    __shared__ float s0[64][32], s1[64][32];
    const int y  = blockIdx.x;
    const int c0 = blockIdx.y * 64;
    const int n  = blockIdx.z;

    const float step = 31.0f / 63.0f;
    const float fy = y * step;
    const int y0 = (int)fy;
    const int y1 = min(y0 + 1, 31);
    const float wy = fy - y0;

    for (int it = threadIdx.x; it < 4096; it += 256) {
        int c = it >> 6, r = (it >> 5) & 1, x = it & 31;
        const float* sp = tx + (((size_t)(n * 256 + c0 + c) * 32) + (r ? y1 : y0)) * 32;
        if (r) s1[c][x] = sp[x]; else s0[c][x] = sp[x];
    }
    __syncthreads();

    for (int it = threadIdx.x; it < 4096; it += 256) {
        int x = it >> 6, c = it & 63;
        float fx = x * step;
        int x0 = (int)fx;  float wx = fx - x0;
        int x1 = min(x0 + 1, 31);
        float top = s0[c][x0] * (1.f - wx) + s0[c][x1] * wx;
        float bot = s1[c][x0] * (1.f - wx) + s1[c][x1] * wx;
        g_txuf[((size_t)n * HW + y * 64 + x) * 256 + c0 + c] =
            __float2half(top * (1.f - wy) + bot * wy);
    }
}

// ---------------------------------------------------------------------------
// transpose + fp16: [n][256][4096] fp32 -> [n*4096][256] fp16 (3 sources)
// ---------------------------------------------------------------------------
__global__ __launch_bounds__(256) void cvt3_k(
    const float* __restrict__ sx1, const float* __restrict__ t_hx,
    const float* __restrict__ sx2)
{
    __shared__ float t[64][65];
    const int src = blockIdx.y >> 2;
    const int c0  = (blockIdx.y & 3) * 64;
    const int n   = blockIdx.z, p0 = blockIdx.x * 64;
    const float* sp = (src == 0 ? sx1 : src == 1 ? t_hx : sx2)
                    + ((size_t)n * 256 + c0) * HW + p0;
    __half* dst = (src == 0 ? g_x1f : src == 1 ? g_thxf : g_x2f);

    for (int it = threadIdx.x; it < 4096; it += 256) {
        int c = it >> 6, px = it & 63;
        t[c][px] = sp[(size_t)c * HW + px];
    }
    __syncthreads();
    for (int it = threadIdx.x; it < 512; it += 256) {
        int px = it >> 3, cg = (it & 7) * 8;
        __half hh[8];
#pragma unroll
        for (int j = 0; j < 8; j++) hh[j] = __float2half(t[cg + j][px]);
        *(uint4*)(dst + ((size_t)n * HW + p0 + px) * 256 + c0 + cg) = *(uint4*)hh;
    }
}

// ---------------------------------------------------------------------------
// weight conversions (single fp16) + g_sum zeroing
// ---------------------------------------------------------------------------
__global__ __launch_bounds__(256) void split_all_k(
    const float* __restrict__ a, const float* __restrict__ b,
    const float* __restrict__ c, const float* __restrict__ d,
    const float* __restrict__ e)
{
    if (blockIdx.y == 5) {
        int i = blockIdx.x * 256 + threadIdx.x;
        if (i < 8 * 256) g_sum[i] = 0.f;
        return;
    }
    const float* src; __half* h; int nel;
    switch (blockIdx.y) {
        case 0:  src = a; h = g_wt1; nel = 256 * 768; break;
        case 1:  src = b; h = g_wU;  nel = 256 * 256; break;
        case 2:  src = c; h = g_wV;  nel = 128 * 256; break;
        case 3:  src = d; h = g_wa1; nel = 128 * 640; break;
        default: src = e; h = g_wa2; nel = 640 * 128; break;
    }
    for (int i = blockIdx.x * 256 + threadIdx.x; i < nel; i += gridDim.x * 256)
        h[i] = __float2half(src[i]);
}

// conv weights: [oc][c][ky][kx] fp32 -> tap-major [oc][tap*640+c] fp16
__global__ __launch_bounds__(256) void cvt_w_k(const float* __restrict__ W)
{
    const int oc = blockIdx.x;
    for (int t = threadIdx.x; t < 5760; t += 256) {
        int c = t / 9, tap = t - c * 9;
        g_wf[(size_t)oc * 5760 + (size_t)tap * 640 + c] =
            __float2half(W[(size_t)oc * 5760 + t]);
    }
}

// ---------------------------------------------------------------------------
// Head (squeeze-excite MLP + L2 normalize); writes "w" output tail
// ---------------------------------------------------------------------------
__global__ __launch_bounds__(256) void head_k(
    const float* __restrict__ Wt2, const float* __restrict__ Wt3,
    float* __restrict__ outw)
{
    const int n = blockIdx.x, tid = threadIdx.x;
    __shared__ float w1[256], w2[64], red[256];

    w1[tid] = g_sum[n * 256 + tid] * (1.f / 4096.f);
    __syncthreads();

    if (tid < 64) {
        float s = 0.f;
#pragma unroll 8
        for (int k = 0; k < 256; k++) s = fmaf(Wt2[tid * 256 + k], w1[k], s);
        w2[tid] = fmaxf(s, 0.f);
    }
    __syncthreads();

    float s = 0.f;
#pragma unroll
    for (int e = 0; e < 64; e++) s = fmaf(Wt3[tid * 64 + e], w2[e], s);

    red[tid] = s * s;
    __syncthreads();
    for (int off = 128; off > 0; off >>= 1) {
        if (tid < off) red[tid] += red[tid + off];
        __syncthreads();
    }
    float nv = sqrtf(red[0]);
    float wv = s / fmaxf(nv, 1e-12f);
    g_w[n * 256 + tid] = wv;
    outw[n * 256 + tid] = wv;
}

// ---------------------------------------------------------------------------
// Unified mma.sync 1x1-conv GEMM, single-pass fp16.
//   CTA 64oc x 256px, 256 threads / 8 warps (2m x 4n), 2 CTAs/SM.
//   4-stage ring, prefetch distance 3; __syncthreads BEFORE staging makes
//   writing buffer (i-1)&3 legal (all warps done reading it).
// ---------------------------------------------------------------------------
#define TILE_A   5120                  // A: 64 rows x 80B
#define TILE_BB  20480                 // B: 256 rows x 80B
#define ST2      (TILE_A + TILE_BB)    // 25600
#define NST      4
#define GEMM_SMEM (NST * ST2)          // 102400 bytes

template<int MODE>
__device__ __forceinline__ void gemm_body(
    int K, int COUT,
    const __half* s0, int st0,
    const __half* s1, int st1,
    const __half* s2, int st2,
    int kb0, int kb1,
    const __half* wp,
    const float* __restrict__ bias,
    __half* __restrict__ of)
{
    extern __shared__ __align__(128) char smem[];
    const uint32_t sb = smem_to_u32(smem);

    const int tid  = threadIdx.x;
    const int lane = tid & 31;
    const int wid  = tid >> 5;
    const int wm   = wid & 1;
    const int wn   = wid >> 1;
    const int n    = blockIdx.z;
    const int ocb  = blockIdx.y * 64;
    const int p0   = blockIdx.x * 256;

    const int bpr0 = wn * 64 + (lane >> 4) * 8 + (lane & 7);
    const uint32_t bkadd = (uint32_t)(((lane >> 3) & 1) * 16);

    float acc[2][8][4];
#pragma unroll
    for (int mi = 0; mi < 2; mi++)
#pragma unroll
        for (int ni = 0; ni < 8; ni++)
#pragma unroll
            for (int r = 0; r < 4; r++) acc[mi][ni][r] = 0.f;

    auto stage = [&](int chunk) {
        const uint32_t base = sb + (chunk & 3) * ST2;
        const int k0 = chunk * 32;
        const __half* sh; int stride, ks;
        if (k0 < kb0)      { sh = s0; stride = st0; ks = 0;   }
        else if (k0 < kb1) { sh = s1; stride = st1; ks = kb0; }
        else               { sh = s2; stride = st2; ks = kb1; }
        const int c0 = k0 - ks;
        {   // A: 64 rows x 4 segs = 256 ops
            int row = tid >> 2, seg = tid & 3;
            cp16(base + row * 80 + seg * 16,
                 wp + (size_t)(ocb + row) * K + k0 + seg * 8, 16);
        }
#pragma unroll
        for (int it = tid; it < 1024; it += 256) {   // B: 256 rows x 4 segs
            int row = it >> 2, seg = it & 3;
            cp16(base + TILE_A + row * 80 + seg * 16,
                 sh + ((size_t)n * HW + p0 + row) * stride + c0 + seg * 8, 16);
        }
    };

    const int NC = K >> 5;
    stage(0); cp_commit();
    stage(1); cp_commit();
    stage(2); cp_commit();

    for (int i = 0; i < NC; i++) {
        if (i + 2 < NC)      cp_wait<2>();
        else if (i + 1 < NC) cp_wait<1>();
        else                 cp_wait<0>();
        __syncthreads();
        if (i + 3 < NC) { stage(i + 3); cp_commit(); }

        const uint32_t base = sb + (i & 3) * ST2;
        const uint32_t aA = base;
        const uint32_t aB = base + TILE_A;

#pragma unroll
        for (int ks = 0; ks < 2; ks++) {
            const int kb = ks * 32;
            uint32_t ah[2][4];
#pragma unroll
            for (int mi = 0; mi < 2; mi++) {
                uint32_t ro = (uint32_t)(wm * 32 + mi * 16 + (lane & 15)) * 80
                            + (uint32_t)(lane >> 4) * 16 + kb;
                ldm_x4(ah[mi], aA + ro);
            }
#pragma unroll
            for (int q = 0; q < 4; q++) {
                uint32_t bro = (uint32_t)(bpr0 + q * 16) * 80 + kb + bkadd;
                uint32_t br[4];
                ldm_x4(br, aB + bro);
#pragma unroll
                for (int mi = 0; mi < 2; mi++) {
                    mma_f16(acc[mi][2 * q],     ah[mi], br[0], br[1]);
                    mma_f16(acc[mi][2 * q + 1], ah[mi], br[2], br[3]);
                }
            }
        }
    }

    if (MODE == 0) {
#pragma unroll
        for (int mi = 0; mi < 2; mi++) {
            int r0 = ocb + wm * 32 + mi * 16 + (lane >> 2);
            float b0 = bias[r0], b1 = bias[r0 + 8];
            float s0v = 0.f, s1v = 0.f;
#pragma unroll
            for (int ni = 0; ni < 8; ni++) {
                s0v += fmaxf(acc[mi][ni][0] + b0, 0.f) + fmaxf(acc[mi][ni][1] + b0, 0.f);
                s1v += fmaxf(acc[mi][ni][2] + b1, 0.f) + fmaxf(acc[mi][ni][3] + b1, 0.f);
            }
            s0v += __shfl_xor_sync(0xffffffffu, s0v, 1);
            s0v += __shfl_xor_sync(0xffffffffu, s0v, 2);
            s1v += __shfl_xor_sync(0xffffffffu, s1v, 1);
            s1v += __shfl_xor_sync(0xffffffffu, s1v, 2);
            if ((lane & 3) == 0) {
                atomicAdd(&g_sum[n * 256 + r0],     s0v);
                atomicAdd(&g_sum[n * 256 + r0 + 8], s1v);
            }
        }
        return;
    }

    // transpose epilogue: two 32px halves per warp, 32x32 patch in smem
    __syncthreads();
    float* patch = (float*)smem + wid * (32 * 33);
    const int oc0 = ocb + wm * 32;

#pragma unroll
    for (int h = 0; h < 2; h++) {
#pragma unroll
        for (int mi = 0; mi < 2; mi++)
#pragma unroll
            for (int nl = 0; nl < 4; nl++) {
                int ni = h * 4 + nl;
                int r = mi * 16 + (lane >> 2);
                int p = nl * 8 + (lane & 3) * 2;
                patch[r * 33 + p]           = acc[mi][ni][0];
                patch[r * 33 + p + 1]       = acc[mi][ni][1];
                patch[(r + 8) * 33 + p]     = acc[mi][ni][2];
                patch[(r + 8) * 33 + p + 1] = acc[mi][ni][3];
            }
        __syncwarp();

        const int pxg = p0 + wn * 64 + h * 32 + lane;
        __half ff[32];
        if (MODE == 3) {
            const __half* gp; int gst, gks;
            if (oc0 < 128)      { gp = g_b2f;  gst = 128; gks = 0;   }
            else if (oc0 < 384) { gp = g_thxf; gst = 256; gks = 128; }
            else                { gp = g_txuf; gst = 256; gks = 384; }
            const __half* gr = gp + ((size_t)n * HW + pxg) * gst + (oc0 - gks);
#pragma unroll
            for (int j = 0; j < 32; j++) {
                float v = patch[j * 33 + lane] + bias[oc0 + j];
                float sg = 1.f / (1.f + expf(-v));
                ff[j] = __float2half(sg * __half2float(gr[j]));
            }
        } else {
#pragma unroll
            for (int j = 0; j < 32; j++) {
                float v = patch[j * 33 + lane] + bias[oc0 + j];
                v = fmaxf(v, 0.f);
                if (MODE == 1) v *= g_w[n * 256 + oc0 + j];
                ff[j] = __float2half(v);
            }
        }
        size_t o = ((size_t)n * HW + pxg) * COUT + oc0;
#pragma unroll
        for (int q = 0; q < 4; q++)
            *(uint4*)(of + o + q * 8) = ((const uint4*)ff)[q];
        __syncwarp();
    }
}

// ----- wrappers -------------------------------------------------------------
__global__ __launch_bounds__(256, 2) void g_stageA_k(const float* __restrict__ bias)
{
    gemm_body<0>(768, 256, g_x1f, 256, g_thxf, 256, g_txuf, 256, 256, 512,
                 g_wt1, bias, nullptr);
}
__global__ __launch_bounds__(256, 2) void g_b1_k(const float* __restrict__ bias)
{
    gemm_body<1>(256, 256, g_x2f, 256, nullptr, 0, nullptr, 0, 256, 256,
                 g_wU, bias, g_b1f);
}
__global__ __launch_bounds__(256, 2) void g_b2_k(const float* __restrict__ bias)
{
    gemm_body<2>(256, 128, g_b1f, 256, nullptr, 0, nullptr, 0, 256, 256,
                 g_wV, bias, g_b2f);
}
__global__ __launch_bounds__(256, 2) void g_a1_k(const float* __restrict__ bias)
{
    gemm_body<2>(640, 128, g_b2f, 128, g_thxf, 256, g_txuf, 256, 128, 384,
                 g_wa1, bias, g_a1f);
}
__global__ __launch_bounds__(256, 2) void g_a2_k(const float* __restrict__ bias)
{
    gemm_body<3>(128, 640, g_a1f, 128, nullptr, 0, nullptr, 0, 128, 128,
                 g_wa2, bias, g_aT_f);
}

// ---------------------------------------------------------------------------
// mma.sync conv3x3, single-pass fp16, CTA 64oc x 256px, halo-shared B.
//   Same barrier-before-stage schedule; next halo staged in 6 uniform
//   parts during steps j=0..5 of the current chunk (after the barrier,
//   so writes to parity (cc+1)&1 cannot race reads of (cc-1)&1).
// ---------------------------------------------------------------------------
#define CONV_A_TILE 5120               // 64 rows x 80B
#define CONV_B_TILE (396 * 80)         // 31680: 6x66 halo rows x 80B
#define CONV_SMEM   (4 * CONV_A_TILE + 2 * CONV_B_TILE)   // 83840

__global__ __launch_bounds__(256, 2) void mma_conv3_k(
    const float* __restrict__ bot, float* __restrict__ out)
{
    extern __shared__ __align__(128) char smem[];
    const uint32_t sb  = smem_to_u32(smem);
    const uint32_t sbB = sb + 4 * CONV_A_TILE;

    const int tid  = threadIdx.x;
    const int lane = tid & 31;
    const int wid  = tid >> 5;
    const int wm   = wid & 1;
    const int wn   = wid >> 1;
    const int n    = blockIdx.z;
    const int ocb  = blockIdx.y * 64;
    const int by4  = blockIdx.x * 4;   // 4 output rows
    const int p0   = blockIdx.x * 256;

    const int bpr0 = wn * 64 + (lane >> 4) * 8 + (lane & 7);
    const uint32_t bkadd = (uint32_t)(((lane >> 3) & 1) * 16);

    float acc[2][8][4];
#pragma unroll
    for (int mi = 0; mi < 2; mi++)
#pragma unroll
        for (int ni = 0; ni < 8; ni++)
#pragma unroll
            for (int r = 0; r < 4; r++) acc[mi][ni][r] = 0.f;

    auto stageA = [&](int s) {
        const uint32_t base = sb + (s & 3) * CONV_A_TILE;
        const int tap = s % 9, cc = s / 9;
        const int koff = tap * 640 + cc * 32;
        int row = tid >> 2, seg = tid & 3;
        cp16(base + row * 80 + seg * 16,
             g_wf + (size_t)(ocb + row) * 5760 + koff + seg * 8, 16);
    };
    auto stageBpart = [&](int cc, int r0, int nr) {
        const uint32_t base = sbB + (cc & 1) * CONV_B_TILE;
        const int c0 = cc * 32;
        for (int it = tid; it < nr * 4; it += 256) {
            int hrow = r0 + (it >> 2), seg = it & 3;   // hrow = ry*66 + rx
            int ry = hrow / 66, rx = hrow - ry * 66;
            int iy = by4 - 1 + ry, ix = rx - 1;
            bool ok = ((unsigned)iy < 64u) && ((unsigned)ix < 64u);
            const __half* src = ok
                ? g_aT_f + ((size_t)(n * HW + iy * 64 + ix)) * 640 + c0 + seg * 8
                : g_aT_f;
            cp16(base + hrow * 80 + seg * 16, src, ok ? 16u : 0u);
        }
    };

    const int NS = 180;                // 20 chunks x 9 taps
    stageBpart(0, 0, 396);             // full halo for cc = 0
    stageA(0); cp_commit();
    stageA(1); cp_commit();
    stageA(2); cp_commit();

    for (int s = 0; s < NS; s++) {
        if (s + 2 < NS)      cp_wait<2>();
        else if (s + 1 < NS) cp_wait<1>();
        else                 cp_wait<0>();
        __syncthreads();
        if (s + 3 < NS) {
            stageA(s + 3);
            int j = s % 9, cc = s / 9;
            if (j < 6 && cc + 1 < 20) stageBpart(cc + 1, j * 66, 66);
            cp_commit();
        }

        const int tap = s % 9;
        const int dy = tap / 3 - 1, dx = tap % 3 - 1;
        const uint32_t aA = sb + (s & 3) * CONV_A_TILE;
        const uint32_t aB = sbB + ((s / 9) & 1) * CONV_B_TILE;

        uint32_t bro[4];
#pragma unroll
        for (int q = 0; q < 4; q++) {
            int pr = bpr0 + q * 16;
            int hrow = ((pr >> 6) + dy + 1) * 66 + (pr & 63) + dx + 1;
            bro[q] = (uint32_t)hrow * 80 + bkadd;
        }

#pragma unroll
        for (int ks = 0; ks < 2; ks++) {
            const int kb = ks * 32;
            uint32_t ah[2][4];
#pragma unroll
            for (int mi = 0; mi < 2; mi++) {
                uint32_t ro = (uint32_t)(wm * 32 + mi * 16 + (lane & 15)) * 80
                            + (uint32_t)(lane >> 4) * 16 + kb;
                ldm_x4(ah[mi], aA + ro);
            }
#pragma unroll
            for (int q = 0; q < 4; q++) {
                uint32_t br[4];
                ldm_x4(br, aB + bro[q] + kb);
#pragma unroll
                for (int mi = 0; mi < 2; mi++) {
                    mma_f16(acc[mi][2 * q],     ah[mi], br[0], br[1]);
                    mma_f16(acc[mi][2 * q + 1], ah[mi], br[2], br[3]);
                }
            }
        }
    }

    const size_t nb = (size_t)n * 256 * HW;
#pragma unroll
    for (int mi = 0; mi < 2; mi++) {
        int r0 = ocb + wm * 32 + mi * 16 + (lane >> 2);
        float bv0 = bot[r0], bv1 = bot[r0 + 8];
#pragma unroll
        for (int ni = 0; ni < 8; ni++) {
            int px = p0 + wn * 64 + ni * 8 + (lane & 3) * 2;
            float2 v0, v1;
            v0.x = fmaxf(acc[mi][ni][0] + bv0, 0.f);
            v0.y = fmaxf(acc[mi][ni][1] + bv0, 0.f);
            v1.x = fmaxf(acc[mi][ni][2] + bv1, 0.f);
            v1.y = fmaxf(acc[mi][ni][3] + bv1, 0.f);
            *(float2*)(out + nb + (size_t)r0 * HW + px)       = v0;
            *(float2*)(out + nb + (size_t)(r0 + 8) * HW + px) = v1;
        }
    }
}

// ---------------------------------------------------------------------------
// Launch  (g_stageA_k in profiled 4th slot)
// ---------------------------------------------------------------------------
extern "C" void kernel_launch(void* const* d_in, const int* in_sizes, int n_in,
                              void* d_out, int out_size)
{
    const float* sx1  = (const float*)d_in[0];
    const float* sx2  = (const float*)d_in[1];
    const float* t_hx = (const float*)d_in[2];
    const float* tx   = (const float*)d_in[3];
    const float* W_t1 = (const float*)d_in[4];
    const float* b_t1 = (const float*)d_in[5];
    const float* W_t2 = (const float*)d_in[6];
    const float* W_t3 = (const float*)d_in[7];
    const float* W_U  = (const float*)d_in[8];
    const float* b_U  = (const float*)d_in[9];
    const float* W_V  = (const float*)d_in[10];
    const float* b_V  = (const float*)d_in[11];
    const float* W_a1 = (const float*)d_in[12];
    const float* b_a1 = (const float*)d_in[13];
    const float* W_a2 = (const float*)d_in[14];
    const float* b_a2 = (const float*)d_in[15];
    const float* W_ot = (const float*)d_in[16];
    const float* b_ot = (const float*)d_in[17];
    float* out = (float*)d_out;

    cudaFuncSetAttribute(g_stageA_k,  cudaFuncAttributeMaxDynamicSharedMemorySize, GEMM_SMEM);
    cudaFuncSetAttribute(g_b1_k,      cudaFuncAttributeMaxDynamicSharedMemorySize, GEMM_SMEM);
    cudaFuncSetAttribute(g_b2_k,      cudaFuncAttributeMaxDynamicSharedMemorySize, GEMM_SMEM);
    cudaFuncSetAttribute(g_a1_k,      cudaFuncAttributeMaxDynamicSharedMemorySize, GEMM_SMEM);
    cudaFuncSetAttribute(g_a2_k,      cudaFuncAttributeMaxDynamicSharedMemorySize, GEMM_SMEM);
    cudaFuncSetAttribute(mma_conv3_k, cudaFuncAttributeMaxDynamicSharedMemorySize, CONV_SMEM);

    // 1-3: conversions needed by stage A
    split_all_k<<<dim3(96, 6), 256>>>(W_t1, W_U, W_V, W_a1, W_a2);
    ups_cvt_k<<<dim3(64, 4, 8), 256>>>(tx);
    cvt3_k<<<dim3(64, 12, 8), 256>>>(sx1, t_hx, sx2);
    // 4: stage A GEMM + GAP  (profiled slot)
    g_stageA_k<<<dim3(16, 4, 8), 256, GEMM_SMEM>>>(b_t1);
    // head MLP + normalize
    head_k<<<8, 256>>>(W_t2, W_t3, out + OUT_A_ELEMS);
    // b1 = relu(W_U@sx2 + b)*w
    g_b1_k<<<dim3(16, 4, 8), 256, GEMM_SMEM>>>(b_U);
    // b2 = relu(W_V@b1 + b)
    g_b2_k<<<dim3(16, 2, 8), 256, GEMM_SMEM>>>(b_V);
    // a1 = relu(W_a1@[b2;thx;txu] + b)
    g_a1_k<<<dim3(16, 2, 8), 256, GEMM_SMEM>>>(b_a1);
    // conv weight reorder (needed only by conv)
    cvt_w_k<<<256, 256>>>(W_ot);
    // apod = sigmoid(W_a2@a1 + b) * bcat -> g_aT_f
    g_a2_k<<<dim3(16, 10, 8), 256, GEMM_SMEM>>>(b_a2);
    // conv3x3 + bias + relu -> main output
    mma_conv3_k<<<dim3(16, 4, 8), 256, CONV_SMEM>>>(b_ot, out);
}

// round 16
// speedup vs baseline: 1.0679x; 1.0679x over previous
#include <cuda_runtime.h>
#include <cuda_fp16.h>
#include <math.h>
#include <stdint.h>

// ---------------------------------------------------------------------------
// Problem constants
// ---------------------------------------------------------------------------
#define HW     4096          // 64*64
#define NB     8
#define OUT_A_ELEMS (8 * 256 * 4096)   // "a" output
// output layout: a [8,256,64,64] followed by w [8,256]

// ---------------------------------------------------------------------------
// Scratch (static device globals -- no allocation allowed)
// ---------------------------------------------------------------------------
__device__ float g_sum [8 * 256];          // stage-A GAP accumulator
__device__ float g_w   [8 * 256];          // normalized channel weights

// fp16 channel-last activation planes [n*4096][C]
__device__ __align__(16) __half g_x1f [8ULL * 4096 * 256];
__device__ __align__(16) __half g_thxf[8ULL * 4096 * 256];
__device__ __align__(16) __half g_txuf[8ULL * 4096 * 256];
__device__ __align__(16) __half g_x2f [8ULL * 4096 * 256];
__device__ __align__(16) __half g_b1f [8ULL * 4096 * 256];
__device__ __align__(16) __half g_b2f [8ULL * 4096 * 128];
__device__ __align__(16) __half g_a1f [8ULL * 4096 * 128];
__device__ __align__(16) __half g_aT_f[8ULL * 4096 * 640];

// fp16 weights (row-major [O][K])
__device__ __align__(16) __half g_wt1[256 * 768];
__device__ __align__(16) __half g_wU [256 * 256];
__device__ __align__(16) __half g_wV [128 * 256];
__device__ __align__(16) __half g_wa1[128 * 640];
__device__ __align__(16) __half g_wa2[640 * 128];
// conv3x3 weights, tap-major [oc][tap*640+c]
__device__ __align__(16) __half g_wf[256 * 5760];

// ---------------------------------------------------------------------------
// helpers
// ---------------------------------------------------------------------------
__device__ __forceinline__ uint32_t smem_to_u32(const void* p) {
    uint32_t a;
    asm("{ .reg .u64 t; cvta.to.shared.u64 t, %1; cvt.u32.u64 %0, t; }"
        : "=r"(a) : "l"(p));
    return a;
}

__device__ __forceinline__ void cp16(uint32_t dst, const void* src, uint32_t bytes) {
    asm volatile("cp.async.cg.shared.global [%0], [%1], 16, %2;"
                 :: "r"(dst), "l"(src), "r"(bytes) : "memory");
}
__device__ __forceinline__ void cp_commit() {
    asm volatile("cp.async.commit_group;" ::: "memory");
}
template<int N>
__device__ __forceinline__ void cp_wait() {
    asm volatile("cp.async.wait_group %0;" :: "n"(N) : "memory");
}

__device__ __forceinline__ void ldm_x4(uint32_t (&r)[4], uint32_t addr) {
    asm volatile("ldmatrix.sync.aligned.m8n8.x4.shared.b16 {%0,%1,%2,%3}, [%4];"
                 : "=r"(r[0]), "=r"(r[1]), "=r"(r[2]), "=r"(r[3]) : "r"(addr));
}

__device__ __forceinline__ void mma_f16(float (&c)[4], const uint32_t (&a)[4],
                                        uint32_t b0, uint32_t b1) {
    asm volatile(
        "mma.sync.aligned.m16n8k16.row.col.f32.f16.f16.f32 "
        "{%0,%1,%2,%3}, {%4,%5,%6,%7}, {%8,%9}, {%0,%1,%2,%3};"
        : "+f"(c[0]), "+f"(c[1]), "+f"(c[2]), "+f"(c[3])
        : "r"(a[0]), "r"(a[1]), "r"(a[2]), "r"(a[3]), "r"(b0), "r"(b1));
}

// ---------------------------------------------------------------------------
// fused upsample x2 (align_corners) + transpose + fp16: tx -> g_txuf
//   float4-vectorized loads for MLP
// ---------------------------------------------------------------------------
__global__ __launch_bounds__(256) void ups_cvt_k(const float* __restrict__ tx)
{
    __shared__ float s0[64][32], s1[64][32];
    const int y  = blockIdx.x;
    const int c0 = blockIdx.y * 64;
    const int n  = blockIdx.z;

    const float step = 31.0f / 63.0f;
    const float fy = y * step;
    const int y0 = (int)fy;
    const int y1 = min(y0 + 1, 31);
    const float wy = fy - y0;

#pragma unroll
    for (int it = threadIdx.x; it < 1024; it += 256) {
        int c = it >> 4, r = (it >> 3) & 1, x4 = (it & 7) * 4;
        const float* sp = tx + (((size_t)(n * 256 + c0 + c) * 32) + (r ? y1 : y0)) * 32 + x4;
        float4 v = *(const float4*)sp;
        float* d = (r ? &s1[c][x4] : &s0[c][x4]);
        d[0] = v.x; d[1] = v.y; d[2] = v.z; d[3] = v.w;
    }
    __syncthreads();

    for (int it = threadIdx.x; it < 4096; it += 256) {
        int x = it >> 6, c = it & 63;
        float fx = x * step;
        int x0 = (int)fx;  float wx = fx - x0;
        int x1 = min(x0 + 1, 31);
        float top = s0[c][x0] * (1.f - wx) + s0[c][x1] * wx;
        float bot = s1[c][x0] * (1.f - wx) + s1[c][x1] * wx;
        g_txuf[((size_t)n * HW + y * 64 + x) * 256 + c0 + c] =
            __float2half(top * (1.f - wy) + bot * wy);
    }
}

// ---------------------------------------------------------------------------
// transpose + fp16: [n][256][4096] fp32 -> [n*4096][256] fp16 (3 sources)
//   float4-vectorized loads for MLP
// ---------------------------------------------------------------------------
__global__ __launch_bounds__(256) void cvt3_k(
    const float* __restrict__ sx1, const float* __restrict__ t_hx,
    const float* __restrict__ sx2)
{
    __shared__ float t[64][68];
    const int src = blockIdx.y >> 2;
    const int c0  = (blockIdx.y & 3) * 64;
    const int n   = blockIdx.z, p0 = blockIdx.x * 64;
    const float* sp = (src == 0 ? sx1 : src == 1 ? t_hx : sx2)
                    + ((size_t)n * 256 + c0) * HW + p0;
    __half* dst = (src == 0 ? g_x1f : src == 1 ? g_thxf : g_x2f);

#pragma unroll
    for (int it = threadIdx.x; it < 1024; it += 256) {
        int c = it >> 4, px4 = (it & 15) * 4;
        float4 v = *(const float4*)(sp + (size_t)c * HW + px4);
        t[c][px4]     = v.x; t[c][px4 + 1] = v.y;
        t[c][px4 + 2] = v.z; t[c][px4 + 3] = v.w;
    }
    __syncthreads();
    for (int it = threadIdx.x; it < 512; it += 256) {
        int px = it >> 3, cg = (it & 7) * 8;
        __half hh[8];
#pragma unroll
        for (int j = 0; j < 8; j++) hh[j] = __float2half(t[cg + j][px]);
        *(uint4*)(dst + ((size_t)n * HW + p0 + px) * 256 + c0 + cg) = *(uint4*)hh;
    }
}

// ---------------------------------------------------------------------------
// weight conversions (single fp16) + g_sum zeroing
// ---------------------------------------------------------------------------
__global__ __launch_bounds__(256) void split_all_k(
    const float* __restrict__ a, const float* __restrict__ b,
    const float* __restrict__ c, const float* __restrict__ d,
    const float* __restrict__ e)
{
    if (blockIdx.y == 5) {
        int i = blockIdx.x * 256 + threadIdx.x;
        if (i < 8 * 256) g_sum[i] = 0.f;
        return;
    }
    const float* src; __half* h; int nel;
    switch (blockIdx.y) {
        case 0:  src = a; h = g_wt1; nel = 256 * 768; break;
        case 1:  src = b; h = g_wU;  nel = 256 * 256; break;
        case 2:  src = c; h = g_wV;  nel = 128 * 256; break;
        case 3:  src = d; h = g_wa1; nel = 128 * 640; break;
        default: src = e; h = g_wa2; nel = 640 * 128; break;
    }
    for (int i = blockIdx.x * 256 + threadIdx.x; i < nel; i += gridDim.x * 256)
        h[i] = __float2half(src[i]);
}

// conv weights: [oc][c][ky][kx] fp32 -> tap-major [oc][tap*640+c] fp16
__global__ __launch_bounds__(256) void cvt_w_k(const float* __restrict__ W)
{
    const int oc = blockIdx.x;
    for (int t = threadIdx.x; t < 5760; t += 256) {
        int c = t / 9, tap = t - c * 9;
        g_wf[(size_t)oc * 5760 + (size_t)tap * 640 + c] =
            __float2half(W[(size_t)oc * 5760 + t]);
    }
}

// ---------------------------------------------------------------------------
// Head (squeeze-excite MLP + L2 normalize); writes "w" output tail
// ---------------------------------------------------------------------------
__global__ __launch_bounds__(256) void head_k(
    const float* __restrict__ Wt2, const float* __restrict__ Wt3,
    float* __restrict__ outw)
{
    const int n = blockIdx.x, tid = threadIdx.x;
    __shared__ float w1[256], w2[64], red[256];

    w1[tid] = g_sum[n * 256 + tid] * (1.f / 4096.f);
    __syncthreads();

    if (tid < 64) {
        float s = 0.f;
#pragma unroll 8
        for (int k = 0; k < 256; k++) s = fmaf(Wt2[tid * 256 + k], w1[k], s);
        w2[tid] = fmaxf(s, 0.f);
    }
    __syncthreads();

    float s = 0.f;
#pragma unroll
    for (int e = 0; e < 64; e++) s = fmaf(Wt3[tid * 64 + e], w2[e], s);

    red[tid] = s * s;
    __syncthreads();
    for (int off = 128; off > 0; off >>= 1) {
        if (tid < off) red[tid] += red[tid + off];
        __syncthreads();
    }
    float nv = sqrtf(red[0]);
    float wv = s / fmaxf(nv, 1e-12f);
    g_w[n * 256 + tid] = wv;
    outw[n * 256 + tid] = wv;
}

// ---------------------------------------------------------------------------
// Unified mma.sync 1x1-conv GEMM, single-pass fp16 (R12 winner: 4-stage
// ring, stage-then-wait, prefetch distance 2).
//   CTA 64oc x 256px, 256 threads / 8 warps (2m x 4n), 2 CTAs/SM.
// ---------------------------------------------------------------------------
#define TILE_A   5120                  // A: 64 rows x 80B
#define TILE_BB  20480                 // B: 256 rows x 80B
#define ST2      (TILE_A + TILE_BB)    // 25600
#define NST      4
#define GEMM_SMEM (NST * ST2)          // 102400 bytes

template<int MODE>
__device__ __forceinline__ void gemm_body(
    int K, int COUT,
    const __half* s0, int st0,
    const __half* s1, int st1,
    const __half* s2, int st2,
    int kb0, int kb1,
    const __half* wp,
    const float* __restrict__ bias,
    __half* __restrict__ of)
{
    extern __shared__ __align__(128) char smem[];
    const uint32_t sb = smem_to_u32(smem);

    const int tid  = threadIdx.x;
    const int lane = tid & 31;
    const int wid  = tid >> 5;
    const int wm   = wid & 1;
    const int wn   = wid >> 1;
    const int n    = blockIdx.z;
    const int ocb  = blockIdx.y * 64;
    const int p0   = blockIdx.x * 256;

    const int bpr0 = wn * 64 + (lane >> 4) * 8 + (lane & 7);
    const uint32_t bkadd = (uint32_t)(((lane >> 3) & 1) * 16);

    float acc[2][8][4];
#pragma unroll
    for (int mi = 0; mi < 2; mi++)
#pragma unroll
        for (int ni = 0; ni < 8; ni++)
#pragma unroll
            for (int r = 0; r < 4; r++) acc[mi][ni][r] = 0.f;

    auto stage = [&](int chunk) {
        const uint32_t base = sb + (chunk & 3) * ST2;
        const int k0 = chunk * 32;
        const __half* sh; int stride, ks;
        if (k0 < kb0)      { sh = s0; stride = st0; ks = 0;   }
        else if (k0 < kb1) { sh = s1; stride = st1; ks = kb0; }
        else               { sh = s2; stride = st2; ks = kb1; }
        const int c0 = k0 - ks;
        {   // A: 64 rows x 4 segs = 256 ops
            int row = tid >> 2, seg = tid & 3;
            cp16(base + row * 80 + seg * 16,
                 wp + (size_t)(ocb + row) * K + k0 + seg * 8, 16);
        }
#pragma unroll
        for (int it = tid; it < 1024; it += 256) {   // B: 256 rows x 4 segs
            int row = it >> 2, seg = it & 3;
            cp16(base + TILE_A + row * 80 + seg * 16,
                 sh + ((size_t)n * HW + p0 + row) * stride + c0 + seg * 8, 16);
        }
    };

    const int NC = K >> 5;
    stage(0); cp_commit();
    stage(1); cp_commit();

    for (int i = 0; i < NC; i++) {
        if (i + 2 < NC)      { stage(i + 2); cp_commit(); cp_wait<2>(); }
        else if (i + 1 < NC) cp_wait<1>();
        else                 cp_wait<0>();
        __syncthreads();

        const uint32_t base = sb + (i & 3) * ST2;
        const uint32_t aA = base;
        const uint32_t aB = base + TILE_A;

#pragma unroll
        for (int ks = 0; ks < 2; ks++) {
            const int kb = ks * 32;
            uint32_t ah[2][4];
#pragma unroll
            for (int mi = 0; mi < 2; mi++) {
                uint32_t ro = (uint32_t)(wm * 32 + mi * 16 + (lane & 15)) * 80
                            + (uint32_t)(lane >> 4) * 16 + kb;
                ldm_x4(ah[mi], aA + ro);
            }
#pragma unroll
            for (int q = 0; q < 4; q++) {
                uint32_t bro = (uint32_t)(bpr0 + q * 16) * 80 + kb + bkadd;
                uint32_t br[4];
                ldm_x4(br, aB + bro);
#pragma unroll
                for (int mi = 0; mi < 2; mi++) {
                    mma_f16(acc[mi][2 * q],     ah[mi], br[0], br[1]);
                    mma_f16(acc[mi][2 * q + 1], ah[mi], br[2], br[3]);
                }
            }
        }
    }

    if (MODE == 0) {
#pragma unroll
        for (int mi = 0; mi < 2; mi++) {
            int r0 = ocb + wm * 32 + mi * 16 + (lane >> 2);
            float b0 = bias[r0], b1 = bias[r0 + 8];
            float s0v = 0.f, s1v = 0.f;
#pragma unroll
            for (int ni = 0; ni < 8; ni++) {
                s0v += fmaxf(acc[mi][ni][0] + b0, 0.f) + fmaxf(acc[mi][ni][1] + b0, 0.f);
                s1v += fmaxf(acc[mi][ni][2] + b1, 0.f) + fmaxf(acc[mi][ni][3] + b1, 0.f);
            }
            s0v += __shfl_xor_sync(0xffffffffu, s0v, 1);
            s0v += __shfl_xor_sync(0xffffffffu, s0v, 2);
            s1v += __shfl_xor_sync(0xffffffffu, s1v, 1);
            s1v += __shfl_xor_sync(0xffffffffu, s1v, 2);
            if ((lane & 3) == 0) {
                atomicAdd(&g_sum[n * 256 + r0],     s0v);
                atomicAdd(&g_sum[n * 256 + r0 + 8], s1v);
            }
        }
        return;
    }

    // transpose epilogue: two 32px halves per warp, 32x32 patch in smem
    __syncthreads();
    float* patch = (float*)smem + wid * (32 * 33);
    const int oc0 = ocb + wm * 32;

#pragma unroll
    for (int h = 0; h < 2; h++) {
#pragma unroll
        for (int mi = 0; mi < 2; mi++)
#pragma unroll
            for (int nl = 0; nl < 4; nl++) {
                int ni = h * 4 + nl;
                int r = mi * 16 + (lane >> 2);
                int p = nl * 8 + (lane & 3) * 2;
                patch[r * 33 + p]           = acc[mi][ni][0];
                patch[r * 33 + p + 1]       = acc[mi][ni][1];
                patch[(r + 8) * 33 + p]     = acc[mi][ni][2];
                patch[(r + 8) * 33 + p + 1] = acc[mi][ni][3];
            }
        __syncwarp();

        const int pxg = p0 + wn * 64 + h * 32 + lane;
        __half ff[32];
        if (MODE == 3) {
            const __half* gp; int gst, gks;
            if (oc0 < 128)      { gp = g_b2f;  gst = 128; gks = 0;   }
            else if (oc0 < 384) { gp = g_thxf; gst = 256; gks = 128; }
            else                { gp = g_txuf; gst = 256; gks = 384; }
            const __half* gr = gp + ((size_t)n * HW + pxg) * gst + (oc0 - gks);
#pragma unroll
            for (int j = 0; j < 32; j++) {
                float v = patch[j * 33 + lane] + bias[oc0 + j];
                float sg = 1.f / (1.f + expf(-v));
                ff[j] = __float2half(sg * __half2float(gr[j]));
            }
        } else {
#pragma unroll
            for (int j = 0; j < 32; j++) {
                float v = patch[j * 33 + lane] + bias[oc0 + j];
                v = fmaxf(v, 0.f);
                if (MODE == 1) v *= g_w[n * 256 + oc0 + j];
                ff[j] = __float2half(v);
            }
        }
        size_t o = ((size_t)n * HW + pxg) * COUT + oc0;
#pragma unroll
        for (int q = 0; q < 4; q++)
            *(uint4*)(of + o + q * 8) = ((const uint4*)ff)[q];
        __syncwarp();
    }
}

// ----- wrappers -------------------------------------------------------------
__global__ __launch_bounds__(256, 2) void g_stageA_k(const float* __restrict__ bias)
{
    gemm_body<0>(768, 256, g_x1f, 256, g_thxf, 256, g_txuf, 256, 256, 512,
                 g_wt1, bias, nullptr);
}
__global__ __launch_bounds__(256, 2) void g_b1_k(const float* __restrict__ bias)
{
    gemm_body<1>(256, 256, g_x2f, 256, nullptr, 0, nullptr, 0, 256, 256,
                 g_wU, bias, g_b1f);
}
__global__ __launch_bounds__(256, 2) void g_b2_k(const float* __restrict__ bias)
{
    gemm_body<2>(256, 128, g_b1f, 256, nullptr, 0, nullptr, 0, 256, 256,
                 g_wV, bias, g_b2f);
}
__global__ __launch_bounds__(256, 2) void g_a1_k(const float* __restrict__ bias)
{
    gemm_body<2>(640, 128, g_b2f, 128, g_thxf, 256, g_txuf, 256, 128, 384,
                 g_wa1, bias, g_a1f);
}
__global__ __launch_bounds__(256, 2) void g_a2_k(const float* __restrict__ bias)
{
    gemm_body<3>(128, 640, g_a1f, 128, nullptr, 0, nullptr, 0, 128, 128,
                 g_wa2, bias, g_aT_f);
}

// ---------------------------------------------------------------------------
// mma.sync conv3x3, single-pass fp16 (R12 winner), CTA 64oc x 256px,
// halo-shared B, stage-then-wait distance-2.
// ---------------------------------------------------------------------------
#define CONV_A_TILE 5120               // 64 rows x 80B
#define CONV_B_TILE (396 * 80)         // 31680: 6x66 halo rows x 80B
#define CONV_SMEM   (4 * CONV_A_TILE + 2 * CONV_B_TILE)   // 83840

__global__ __launch_bounds__(256, 2) void mma_conv3_k(
    const float* __restrict__ bot, float* __restrict__ out)
{
    extern __shared__ __align__(128) char smem[];
    const uint32_t sb  = smem_to_u32(smem);
    const uint32_t sbB = sb + 4 * CONV_A_TILE;

    const int tid  = threadIdx.x;
    const int lane = tid & 31;
    const int wid  = tid >> 5;
    const int wm   = wid & 1;
    const int wn   = wid >> 1;
    const int n    = blockIdx.z;
    const int ocb  = blockIdx.y * 64;
    const int by4  = blockIdx.x * 4;   // 4 output rows
    const int p0   = blockIdx.x * 256;

    const int bpr0 = wn * 64 + (lane >> 4) * 8 + (lane & 7);
    const uint32_t bkadd = (uint32_t)(((lane >> 3) & 1) * 16);

    float acc[2][8][4];
#pragma unroll
    for (int mi = 0; mi < 2; mi++)
#pragma unroll
        for (int ni = 0; ni < 8; ni++)
#pragma unroll
            for (int r = 0; r < 4; r++) acc[mi][ni][r] = 0.f;

    auto stageA = [&](int s) {
        const uint32_t base = sb + (s & 3) * CONV_A_TILE;
        const int tap = s % 9, cc = s / 9;
        const int koff = tap * 640 + cc * 32;
        int row = tid >> 2, seg = tid & 3;
        cp16(base + row * 80 + seg * 16,
             g_wf + (size_t)(ocb + row) * 5760 + koff + seg * 8, 16);
    };
    auto stageB = [&](int cc) {
        const uint32_t base = sbB + (cc & 1) * CONV_B_TILE;
        const int c0 = cc * 32;
        for (int it = tid; it < 1584; it += 256) {
            int hrow = it >> 2, seg = it & 3;        // hrow = ry*66 + rx
            int ry = hrow / 66, rx = hrow - ry * 66;
            int iy = by4 - 1 + ry, ix = rx - 1;
            bool ok = ((unsigned)iy < 64u) && ((unsigned)ix < 64u);
            const __half* src = ok
                ? g_aT_f + ((size_t)(n * HW + iy * 64 + ix)) * 640 + c0 + seg * 8
                : g_aT_f;
            cp16(base + hrow * 80 + seg * 16, src, ok ? 16u : 0u);
        }
    };

    const int NS = 180;                // 20 chunks x 9 taps
    stageB(0); stageA(0); cp_commit();
    stageA(1); cp_commit();

    for (int s = 0; s < NS; s++) {
        if (s + 2 < NS) {
            stageA(s + 2);
            if ((s + 2) % 9 == 0) stageB((s + 2) / 9);
            cp_commit(); cp_wait<2>();
        } else if (s + 1 < NS) cp_wait<1>();
        else                   cp_wait<0>();
        __syncthreads();

        const int tap = s % 9;
        const int dy = tap / 3 - 1, dx = tap % 3 - 1;
        const uint32_t aA = sb + (s & 3) * CONV_A_TILE;
        const uint32_t aB = sbB + ((s / 9) & 1) * CONV_B_TILE;

        uint32_t bro[4];
#pragma unroll
        for (int q = 0; q < 4; q++) {
            int pr = bpr0 + q * 16;
            int hrow = ((pr >> 6) + dy + 1) * 66 + (pr & 63) + dx + 1;
            bro[q] = (uint32_t)hrow * 80 + bkadd;
        }

#pragma unroll
        for (int ks = 0; ks < 2; ks++) {
            const int kb = ks * 32;
            uint32_t ah[2][4];
#pragma unroll
            for (int mi = 0; mi < 2; mi++) {
                uint32_t ro = (uint32_t)(wm * 32 + mi * 16 + (lane & 15)) * 80
                            + (uint32_t)(lane >> 4) * 16 + kb;
                ldm_x4(ah[mi], aA + ro);
            }
#pragma unroll
            for (int q = 0; q < 4; q++) {
                uint32_t br[4];
                ldm_x4(br, aB + bro[q] + kb);
#pragma unroll
                for (int mi = 0; mi < 2; mi++) {
                    mma_f16(acc[mi][2 * q],     ah[mi], br[0], br[1]);
                    mma_f16(acc[mi][2 * q + 1], ah[mi], br[2], br[3]);
                }
            }
        }
    }

    const size_t nb = (size_t)n * 256 * HW;
#pragma unroll
    for (int mi = 0; mi < 2; mi++) {
        int r0 = ocb + wm * 32 + mi * 16 + (lane >> 2);
        float bv0 = bot[r0], bv1 = bot[r0 + 8];
#pragma unroll
        for (int ni = 0; ni < 8; ni++) {
            int px = p0 + wn * 64 + ni * 8 + (lane & 3) * 2;
            float2 v0, v1;
            v0.x = fmaxf(acc[mi][ni][0] + bv0, 0.f);
            v0.y = fmaxf(acc[mi][ni][1] + bv0, 0.f);
            v1.x = fmaxf(acc[mi][ni][2] + bv1, 0.f);
            v1.y = fmaxf(acc[mi][ni][3] + bv1, 0.f);
            *(float2*)(out + nb + (size_t)r0 * HW + px)       = v0;
            *(float2*)(out + nb + (size_t)(r0 + 8) * HW + px) = v1;
        }
    }
}

// ---------------------------------------------------------------------------
// Launch  (g_stageA_k in profiled 4th slot)
// ---------------------------------------------------------------------------
extern "C" void kernel_launch(void* const* d_in, const int* in_sizes, int n_in,
                              void* d_out, int out_size)
{
    const float* sx1  = (const float*)d_in[0];
    const float* sx2  = (const float*)d_in[1];
    const float* t_hx = (const float*)d_in[2];
    const float* tx   = (const float*)d_in[3];
    const float* W_t1 = (const float*)d_in[4];
    const float* b_t1 = (const float*)d_in[5];
    const float* W_t2 = (const float*)d_in[6];
    const float* W_t3 = (const float*)d_in[7];
    const float* W_U  = (const float*)d_in[8];
    const float* b_U  = (const float*)d_in[9];
    const float* W_V  = (const float*)d_in[10];
    const float* b_V  = (const float*)d_in[11];
    const float* W_a1 = (const float*)d_in[12];
    const float* b_a1 = (const float*)d_in[13];
    const float* W_a2 = (const float*)d_in[14];
    const float* b_a2 = (const float*)d_in[15];
    const float* W_ot = (const float*)d_in[16];
    const float* b_ot = (const float*)d_in[17];
    float* out = (float*)d_out;

    cudaFuncSetAttribute(g_stageA_k,  cudaFuncAttributeMaxDynamicSharedMemorySize, GEMM_SMEM);
    cudaFuncSetAttribute(g_b1_k,      cudaFuncAttributeMaxDynamicSharedMemorySize, GEMM_SMEM);
    cudaFuncSetAttribute(g_b2_k,      cudaFuncAttributeMaxDynamicSharedMemorySize, GEMM_SMEM);
    cudaFuncSetAttribute(g_a1_k,      cudaFuncAttributeMaxDynamicSharedMemorySize, GEMM_SMEM);
    cudaFuncSetAttribute(g_a2_k,      cudaFuncAttributeMaxDynamicSharedMemorySize, GEMM_SMEM);
    cudaFuncSetAttribute(mma_conv3_k, cudaFuncAttributeMaxDynamicSharedMemorySize, CONV_SMEM);

    // 1-3: conversions needed by stage A
    split_all_k<<<dim3(96, 6), 256>>>(W_t1, W_U, W_V, W_a1, W_a2);
    ups_cvt_k<<<dim3(64, 4, 8), 256>>>(tx);
    cvt3_k<<<dim3(64, 12, 8), 256>>>(sx1, t_hx, sx2);
    // 4: stage A GEMM + GAP  (profiled slot)
    g_stageA_k<<<dim3(16, 4, 8), 256, GEMM_SMEM>>>(b_t1);
    // head MLP + normalize
    head_k<<<8, 256>>>(W_t2, W_t3, out + OUT_A_ELEMS);
    // b1 = relu(W_U@sx2 + b)*w
    g_b1_k<<<dim3(16, 4, 8), 256, GEMM_SMEM>>>(b_U);
    // b2 = relu(W_V@b1 + b)
    g_b2_k<<<dim3(16, 2, 8), 256, GEMM_SMEM>>>(b_V);
    // a1 = relu(W_a1@[b2;thx;txu] + b)
    g_a1_k<<<dim3(16, 2, 8), 256, GEMM_SMEM>>>(b_a1);
    // conv weight reorder (needed only by conv)
    cvt_w_k<<<256, 256>>>(W_ot);
    // apod = sigmoid(W_a2@a1 + b) * bcat -> g_aT_f
    g_a2_k<<<dim3(16, 10, 8), 256, GEMM_SMEM>>>(b_a2);
    // conv3x3 + bias + relu -> main output
    mma_conv3_k<<<dim3(16, 4, 8), 256, CONV_SMEM>>>(b_ot, out);
}